// round 2
// baseline (speedup 1.0000x reference)
#include <cuda_runtime.h>
#include <cstdint>

// ---------------------------------------------------------------------------
// GGUFWeight: out[b,s,n] = sum_k x[b,s,k] * (scale[n,k/32]*(q[n,k]-8)) + bias[n]
// Treated as GEMM: M = B*S = 8192, N = 4096, K = 4096, all fp32.
// Phase 1: dequantize W into a __device__ global fp32 buffer (64 MB).
// Phase 2: 128x128 tiled SIMT fp32 GEMM with fused bias epilogue.
// ---------------------------------------------------------------------------

#define GEMM_BM 128
#define GEMM_BN 128
#define GEMM_BK 16
#define SMEM_PAD 4
#define SMEM_LD (GEMM_BM + SMEM_PAD)   // 132 floats per smem row (528B, 16B-aligned)

// Dequantized weights, [N, K] row-major fp32. 4096*4096*4 = 64 MB.
__device__ float g_W[4096ull * 4096ull];

// ---------------------------------------------------------------------------
// Dequant: w[n,k] = scale[n, k/32] * (q[n,k] - 8). 4 elems/thread via int4.
// K % 32 == 0 so each int4 stays inside one scale block? (k%32 in {0..28},
// 4-aligned -> yes, one scale per int4.)
// ---------------------------------------------------------------------------
__global__ void dequant_kernel(const int* __restrict__ q,
                               const float* __restrict__ scales,
                               int N, int K) {
    size_t idx = ((size_t)blockIdx.x * blockDim.x + threadIdx.x) * 4;
    size_t total = (size_t)N * K;
    if (idx >= total) return;
    int4 qv = *reinterpret_cast<const int4*>(q + idx);
    int k = (int)(idx % (size_t)K);
    int n = (int)(idx / (size_t)K);
    float s = scales[(size_t)n * (K >> 5) + (k >> 5)];
    float4 w;
    w.x = s * (float)(qv.x - 8);
    w.y = s * (float)(qv.y - 8);
    w.z = s * (float)(qv.z - 8);
    w.w = s * (float)(qv.w - 8);
    *reinterpret_cast<float4*>(g_W + idx) = w;
}

// ---------------------------------------------------------------------------
// GEMM: C[m,n] = sum_k A[m,k]*W[n,k] + bias[n]
// Block: 128x128 output tile, BK=16, 256 threads, 8x8 accum per thread using
// the split-quadrant layout (rows ty*4+{0..3} and 64+ty*4+{0..3}; cols
// tx*4+{0..3} and 64+tx*4+{0..3}) so all smem fragment reads are LDS.128
// with conflict-free bank phases.
// Assumes M%128==0, N%128==0, K%16==0 (true: 8192/4096/4096).
// ---------------------------------------------------------------------------
__global__ __launch_bounds__(256, 2)
void gemm_kernel(const float* __restrict__ A,
                 const float* __restrict__ bias,
                 float* __restrict__ C,
                 int M, int N, int K) {
    __shared__ float As[GEMM_BK][SMEM_LD];
    __shared__ float Bs[GEMM_BK][SMEM_LD];

    const int tid = threadIdx.x;
    const int bm = blockIdx.y * GEMM_BM;
    const int bn = blockIdx.x * GEMM_BN;

    const int tx = tid & 15;   // 0..15 -> N direction
    const int ty = tid >> 4;   // 0..15 -> M direction

    float acc[8][8];
#pragma unroll
    for (int i = 0; i < 8; i++)
#pragma unroll
        for (int j = 0; j < 8; j++) acc[i][j] = 0.0f;

    // Global-load mapping: tile is 128 rows x 16 K-cols = 512 float4 loads,
    // 2 per thread. f = tid + l*256; row = f>>2 (0..127), kgroup = f&3.
    const int l_row0 = tid >> 2;          // 0..63
    const int l_kg   = (tid & 3) * 4;     // 0,4,8,12

    const float* Abase = A    + (size_t)(bm + l_row0) * K + l_kg;
    const float* Bbase = g_W  + (size_t)(bn + l_row0) * K + l_kg;
    const size_t rowskip = (size_t)64 * K;   // second load: row + 64

    const int nKt = K / GEMM_BK;
    for (int kt = 0; kt < nKt; kt++) {
        const size_t koff = (size_t)kt * GEMM_BK;

        float4 a0 = *reinterpret_cast<const float4*>(Abase + koff);
        float4 a1 = *reinterpret_cast<const float4*>(Abase + koff + rowskip);
        float4 b0 = *reinterpret_cast<const float4*>(Bbase + koff);
        float4 b1 = *reinterpret_cast<const float4*>(Bbase + koff + rowskip);

        As[l_kg + 0][l_row0] = a0.x;
        As[l_kg + 1][l_row0] = a0.y;
        As[l_kg + 2][l_row0] = a0.z;
        As[l_kg + 3][l_row0] = a0.w;
        As[l_kg + 0][l_row0 + 64] = a1.x;
        As[l_kg + 1][l_row0 + 64] = a1.y;
        As[l_kg + 2][l_row0 + 64] = a1.z;
        As[l_kg + 3][l_row0 + 64] = a1.w;

        Bs[l_kg + 0][l_row0] = b0.x;
        Bs[l_kg + 1][l_row0] = b0.y;
        Bs[l_kg + 2][l_row0] = b0.z;
        Bs[l_kg + 3][l_row0] = b0.w;
        Bs[l_kg + 0][l_row0 + 64] = b1.x;
        Bs[l_kg + 1][l_row0 + 64] = b1.y;
        Bs[l_kg + 2][l_row0 + 64] = b1.z;
        Bs[l_kg + 3][l_row0 + 64] = b1.w;

        __syncthreads();

#pragma unroll
        for (int kk = 0; kk < GEMM_BK; kk++) {
            float a[8], b[8];
            *reinterpret_cast<float4*>(&a[0]) =
                *reinterpret_cast<const float4*>(&As[kk][ty * 4]);
            *reinterpret_cast<float4*>(&a[4]) =
                *reinterpret_cast<const float4*>(&As[kk][64 + ty * 4]);
            *reinterpret_cast<float4*>(&b[0]) =
                *reinterpret_cast<const float4*>(&Bs[kk][tx * 4]);
            *reinterpret_cast<float4*>(&b[4]) =
                *reinterpret_cast<const float4*>(&Bs[kk][64 + tx * 4]);
#pragma unroll
            for (int i = 0; i < 8; i++)
#pragma unroll
                for (int j = 0; j < 8; j++)
                    acc[i][j] = fmaf(a[i], b[j], acc[i][j]);
        }
        __syncthreads();
    }

    // Epilogue: fused bias add, float4 stores.
    float bia[8];
    *reinterpret_cast<float4*>(&bia[0]) =
        *reinterpret_cast<const float4*>(&bias[bn + tx * 4]);
    *reinterpret_cast<float4*>(&bia[4]) =
        *reinterpret_cast<const float4*>(&bias[bn + 64 + tx * 4]);

#pragma unroll
    for (int i = 0; i < 8; i++) {
        const int row = bm + ((i < 4) ? (ty * 4 + i) : (64 + ty * 4 + (i - 4)));
        float4 v0, v1;
        v0.x = acc[i][0] + bia[0];
        v0.y = acc[i][1] + bia[1];
        v0.z = acc[i][2] + bia[2];
        v0.w = acc[i][3] + bia[3];
        v1.x = acc[i][4] + bia[4];
        v1.y = acc[i][5] + bia[5];
        v1.z = acc[i][6] + bia[6];
        v1.w = acc[i][7] + bia[7];
        *reinterpret_cast<float4*>(&C[(size_t)row * N + bn + tx * 4]) = v0;
        *reinterpret_cast<float4*>(&C[(size_t)row * N + bn + 64 + tx * 4]) = v1;
    }
}

// ---------------------------------------------------------------------------
// Launch. Inputs (metadata order): x [B,S,K] f32, qweight [N,K] i32,
// scales [N,K/32] f32, bias [N] f32. Output: [B,S,N] f32.
// ---------------------------------------------------------------------------
extern "C" void kernel_launch(void* const* d_in, const int* in_sizes, int n_in,
                              void* d_out, int out_size) {
    const float* x      = (const float*)d_in[0];
    const int*   qw     = (const int*)d_in[1];
    const float* scales = (const float*)d_in[2];
    const float* bias   = (const float*)d_in[3];
    float*       out    = (float*)d_out;

    const int N = in_sizes[3];                  // 4096
    const int K = in_sizes[1] / N;              // 4096
    const int M = in_sizes[0] / K;              // 8192

    // Phase 1: dequant into g_W
    size_t total = (size_t)N * K;
    int dq_threads = 256;
    int dq_blocks = (int)((total / 4 + dq_threads - 1) / dq_threads);
    dequant_kernel<<<dq_blocks, dq_threads>>>(qw, scales, N, K);

    // Phase 2: GEMM + bias
    dim3 grid(N / GEMM_BN, M / GEMM_BM);
    gemm_kernel<<<grid, 256>>>(x, bias, out, M, N, K);
}

// round 5
// speedup vs baseline: 5.7595x; 5.7595x over previous
#include <cuda_runtime.h>
#include <cuda_fp16.h>
#include <cstdint>

// ===========================================================================
// GGUFWeight on GB300 (target compiles as plain sm_103 -> no tcgen05.ld):
// out[m,n] = sum_k x[m,k] * (scale[n,k/32]*(q[n,k]-8)) + bias[n]
// M = 8192, N = 4096, K = 4096.
// Phase 1: x -> fp16 g_X, dequant W -> fp16 g_W.
// Phase 2: mma.sync.m16n8k16 (HMMA) GEMM, 128x256 CTA tile, BK=32,
//          4-stage cp.async pipeline, ldmatrix.x4 with XOR-swizzled smem,
//          fp32 accumulate, fused bias epilogue.
// ===========================================================================

#define THREADS 256
#define BM 128
#define BN 256
#define BK 32
#define STAGES 4
#define A_STAGE_BYTES (BM * 64)              // 128 rows * 64B (32 halves)
#define B_STAGE_BYTES (BN * 64)              // 256 rows * 64B
#define STAGE_BYTES (A_STAGE_BYTES + B_STAGE_BYTES)   // 24576
#define SMEM_TOTAL (STAGES * STAGE_BYTES)             // 98304

__device__ __half g_X[8192ull * 4096ull];   // [M,K] K-major fp16
__device__ __half g_W[4096ull * 4096ull];   // [N,K] K-major fp16

// ---------------------------------------------------------------------------
__device__ __forceinline__ uint32_t smem_u32(const void* p) {
    uint32_t a;
    asm("{ .reg .u64 t; cvta.to.shared.u64 t, %1; cvt.u32.u64 %0, t; }"
        : "=r"(a) : "l"(p));
    return a;
}

#define CP_ASYNC16(dst, src) \
    asm volatile("cp.async.cg.shared.global [%0], [%1], 16;" \
                 :: "r"(dst), "l"(src) : "memory")
#define CP_COMMIT() asm volatile("cp.async.commit_group;" ::: "memory")
#define CP_WAIT(n)  asm volatile("cp.async.wait_group %0;" :: "n"(n) : "memory")

#define LDSM_X4(r0, r1, r2, r3, addr) \
    asm volatile("ldmatrix.sync.aligned.m8n8.x4.shared.b16 {%0,%1,%2,%3}, [%4];" \
                 : "=r"(r0), "=r"(r1), "=r"(r2), "=r"(r3) : "r"(addr))

#define MMA16816(c0, c1, c2, c3, a0, a1, a2, a3, b0, b1) \
    asm volatile("mma.sync.aligned.m16n8k16.row.col.f32.f16.f16.f32 " \
                 "{%0,%1,%2,%3}, {%4,%5,%6,%7}, {%8,%9}, {%0,%1,%2,%3};" \
                 : "+f"(c0), "+f"(c1), "+f"(c2), "+f"(c3) \
                 : "r"(a0), "r"(a1), "r"(a2), "r"(a3), "r"(b0), "r"(b1))

// ---------------------------------------------------------------------------
// Conversion kernels
// ---------------------------------------------------------------------------
__global__ void convert_x_kernel(const float* __restrict__ x, size_t total) {
    size_t i = ((size_t)blockIdx.x * blockDim.x + threadIdx.x) * 8;
    if (i >= total) return;
    float4 a = *reinterpret_cast<const float4*>(x + i);
    float4 b = *reinterpret_cast<const float4*>(x + i + 4);
    __half h[8];
    h[0] = __float2half_rn(a.x); h[1] = __float2half_rn(a.y);
    h[2] = __float2half_rn(a.z); h[3] = __float2half_rn(a.w);
    h[4] = __float2half_rn(b.x); h[5] = __float2half_rn(b.y);
    h[6] = __float2half_rn(b.z); h[7] = __float2half_rn(b.w);
    *reinterpret_cast<uint4*>(g_X + i) = *reinterpret_cast<uint4*>(h);
}

__global__ void dequant_kernel(const int* __restrict__ q,
                               const float* __restrict__ scales, int K) {
    size_t i = ((size_t)blockIdx.x * blockDim.x + threadIdx.x) * 8;
    int4 q0 = *reinterpret_cast<const int4*>(q + i);
    int4 q1 = *reinterpret_cast<const int4*>(q + i + 4);
    int k = (int)(i % (size_t)K);
    int n = (int)(i / (size_t)K);
    float s = scales[(size_t)n * (K >> 5) + (k >> 5)];
    __half h[8];
    h[0] = __float2half_rn(s * (float)(q0.x - 8));
    h[1] = __float2half_rn(s * (float)(q0.y - 8));
    h[2] = __float2half_rn(s * (float)(q0.z - 8));
    h[3] = __float2half_rn(s * (float)(q0.w - 8));
    h[4] = __float2half_rn(s * (float)(q1.x - 8));
    h[5] = __float2half_rn(s * (float)(q1.y - 8));
    h[6] = __float2half_rn(s * (float)(q1.z - 8));
    h[7] = __float2half_rn(s * (float)(q1.w - 8));
    *reinterpret_cast<uint4*>(g_W + i) = *reinterpret_cast<uint4*>(h);
}

// ---------------------------------------------------------------------------
// HMMA GEMM
// ---------------------------------------------------------------------------
__global__ void __launch_bounds__(THREADS, 1)
gemm_hmma_kernel(const float* __restrict__ bias, float* __restrict__ C,
                 int M, int N, int K) {
    extern __shared__ char smem[];
    const uint32_t smem_base = smem_u32(smem);
    const int tid = threadIdx.x;
    const int wid = tid >> 5;
    const int lane = tid & 31;

    const int bm = blockIdx.y * BM;
    const int bn = blockIdx.x * BN;

    const int warp_m = wid & 1;     // 2 warps over M
    const int warp_n = wid >> 1;    // 4 warps over N

    const __half* gA = g_X + (size_t)bm * K;
    const __half* gB = g_W + (size_t)bn * K;

    // cp.async stage loader: smem rows are 64B (BK=32 halves), 16B chunks
    // swizzled: stored_chunk = chunk ^ ((row>>1)&3)
    auto load_stage = [&](int s, int kc) {
        const uint32_t sA = smem_base + s * STAGE_BYTES;
        const uint32_t sB = sA + A_STAGE_BYTES;
        const __half* gAk = gA + kc * BK;
        const __half* gBk = gB + kc * BK;
#pragma unroll
        for (int i = 0; i < 2; i++) {
            int cid = tid + (i << 8);          // 0..511
            int row = cid >> 2, c = cid & 3;
            int sc = c ^ ((row >> 1) & 3);
            CP_ASYNC16(sA + row * 64 + (sc << 4),
                       gAk + (size_t)row * K + c * 8);
        }
#pragma unroll
        for (int i = 0; i < 4; i++) {
            int cid = tid + (i << 8);          // 0..1023
            int row = cid >> 2, c = cid & 3;
            int sc = c ^ ((row >> 1) & 3);
            CP_ASYNC16(sB + row * 64 + (sc << 4),
                       gBk + (size_t)row * K + c * 8);
        }
        CP_COMMIT();
    };

    // ldmatrix lane constants: lanes 0-7 rows 0-7, 8-15 rows 8-15 (chunk lo),
    // 16-23 rows 0-7, 24-31 rows 8-15 (chunk hi)
    const int rowoff = (lane & 7) + ((lane >> 3) & 1) * 8;   // 0..15
    const int csel   = (lane >> 4) & 1;                      // 0/1
    const int swz    = (rowoff >> 1) & 3;
    // chunk offset bytes within row for k-step ks: ((2*ks + csel) ^ swz) * 16
    const int koff0 = ((0 + csel) ^ swz) << 4;
    const int koff1 = ((2 + csel) ^ swz) << 4;

    const uint32_t aRowByte = (uint32_t)(warp_m * 64 + rowoff) * 64;
    const uint32_t bRowByte = (uint32_t)(warp_n * 64 + rowoff) * 64;

    float acc[4][8][4];
#pragma unroll
    for (int mt = 0; mt < 4; mt++)
#pragma unroll
        for (int j = 0; j < 8; j++)
#pragma unroll
            for (int r = 0; r < 4; r++) acc[mt][j][r] = 0.0f;

    const int nK = K / BK;   // 128 k-chunks

    // Prefetch STAGES-1 stages
#pragma unroll
    for (int s = 0; s < STAGES - 1; s++) load_stage(s, s);

    for (int kc = 0; kc < nK; kc++) {
        const int s = kc & (STAGES - 1);
        CP_WAIT(STAGES - 2);
        __syncthreads();

        if (kc + STAGES - 1 < nK)
            load_stage((kc + STAGES - 1) & (STAGES - 1), kc + STAGES - 1);

        const uint32_t sA = smem_base + s * STAGE_BYTES;
        const uint32_t sB = sA + A_STAGE_BYTES;

#pragma unroll
        for (int ks = 0; ks < 2; ks++) {
            const int koff = ks ? koff1 : koff0;
            uint32_t a[4][4];
#pragma unroll
            for (int mt = 0; mt < 4; mt++)
                LDSM_X4(a[mt][0], a[mt][1], a[mt][2], a[mt][3],
                        sA + aRowByte + mt * 1024 + koff);
            uint32_t b[4][4];
#pragma unroll
            for (int nt = 0; nt < 4; nt++)
                LDSM_X4(b[nt][0], b[nt][1], b[nt][2], b[nt][3],
                        sB + bRowByte + nt * 1024 + koff);
#pragma unroll
            for (int mt = 0; mt < 4; mt++)
#pragma unroll
                for (int j = 0; j < 8; j++) {
                    const int nt = j >> 1, odd = j & 1;
                    MMA16816(acc[mt][j][0], acc[mt][j][1],
                             acc[mt][j][2], acc[mt][j][3],
                             a[mt][0], a[mt][1], a[mt][2], a[mt][3],
                             b[nt][odd], b[nt][2 + odd]);
                }
        }
    }

    // Epilogue: d0,d1 -> (row lane/4, col (lane%4)*2,+1); d2,d3 -> row+8
    const int colb = bn + warp_n * 64 + (lane & 3) * 2;
    float2 brow[8];
#pragma unroll
    for (int j = 0; j < 8; j++)
        brow[j] = *reinterpret_cast<const float2*>(bias + colb + j * 8);

#pragma unroll
    for (int mt = 0; mt < 4; mt++) {
        const int row0 = bm + warp_m * 64 + mt * 16 + (lane >> 2);
#pragma unroll
        for (int j = 0; j < 8; j++) {
            const int col = colb + j * 8;
            float2 v0, v1;
            v0.x = acc[mt][j][0] + brow[j].x;
            v0.y = acc[mt][j][1] + brow[j].y;
            v1.x = acc[mt][j][2] + brow[j].x;
            v1.y = acc[mt][j][3] + brow[j].y;
            *reinterpret_cast<float2*>(C + (size_t)row0 * N + col) = v0;
            *reinterpret_cast<float2*>(C + (size_t)(row0 + 8) * N + col) = v1;
        }
    }
}

// ---------------------------------------------------------------------------
extern "C" void kernel_launch(void* const* d_in, const int* in_sizes, int n_in,
                              void* d_out, int out_size) {
    const float* x      = (const float*)d_in[0];
    const int*   qw     = (const int*)d_in[1];
    const float* scales = (const float*)d_in[2];
    const float* bias   = (const float*)d_in[3];
    float*       out    = (float*)d_out;

    const int N = in_sizes[3];           // 4096
    const int K = in_sizes[1] / N;       // 4096
    const int M = in_sizes[0] / K;       // 8192

    size_t xTotal = (size_t)M * K;
    size_t wTotal = (size_t)N * K;
    convert_x_kernel<<<(unsigned)((xTotal / 8 + 255) / 256), 256>>>(x, xTotal);
    dequant_kernel<<<(unsigned)((wTotal / 8 + 255) / 256), 256>>>(qw, scales, K);

    // 96KB dynamic smem needs opt-in (called unconditionally: deterministic,
    // not a stream op, capture-safe)
    cudaFuncSetAttribute(gemm_hmma_kernel,
                         cudaFuncAttributeMaxDynamicSharedMemorySize, SMEM_TOTAL);

    dim3 grid(N / BN, M / BM);
    gemm_hmma_kernel<<<grid, THREADS, SMEM_TOTAL>>>(bias, out, M, N, K);
}

// round 6
// speedup vs baseline: 6.7639x; 1.1744x over previous
#include <cuda_runtime.h>
#include <cuda_fp16.h>
#include <cstdint>

// ===========================================================================
// GGUFWeight (sm_103 portable path): out = x @ W^T + bias,
// W = scale * (q - 8). M=8192, N=4096, K=4096.
// Phase 1: x -> fp16 g_X, W -> fp16 g_W.
// Phase 2: mma.sync.m16n8k16 GEMM, 128x256 CTA tile, BK=64, 3-stage cp.async,
//          512 threads (16 warps, 4x4 warp grid, 32x64 warp tile),
//          SW128 XOR swizzle + ldmatrix.x4, fp32 accum, fused bias.
// ===========================================================================

#define THREADS 512
#define BM 128
#define BN 256
#define BK 64
#define STAGES 3
#define A_STAGE_BYTES (BM * 128)             // 128 rows * 128B (64 halves)
#define B_STAGE_BYTES (BN * 128)             // 256 rows * 128B
#define STAGE_BYTES (A_STAGE_BYTES + B_STAGE_BYTES)   // 49152
#define SMEM_TOTAL (STAGES * STAGE_BYTES)             // 147456

__device__ __half g_X[8192ull * 4096ull];   // [M,K] K-major fp16
__device__ __half g_W[4096ull * 4096ull];   // [N,K] K-major fp16

// ---------------------------------------------------------------------------
__device__ __forceinline__ uint32_t smem_u32(const void* p) {
    uint32_t a;
    asm("{ .reg .u64 t; cvta.to.shared.u64 t, %1; cvt.u32.u64 %0, t; }"
        : "=r"(a) : "l"(p));
    return a;
}

#define CP_ASYNC16(dst, src) \
    asm volatile("cp.async.cg.shared.global [%0], [%1], 16;" \
                 :: "r"(dst), "l"(src) : "memory")
#define CP_COMMIT() asm volatile("cp.async.commit_group;" ::: "memory")
#define CP_WAIT(n)  asm volatile("cp.async.wait_group %0;" :: "n"(n) : "memory")

#define LDSM_X4(r0, r1, r2, r3, addr) \
    asm volatile("ldmatrix.sync.aligned.m8n8.x4.shared.b16 {%0,%1,%2,%3}, [%4];" \
                 : "=r"(r0), "=r"(r1), "=r"(r2), "=r"(r3) : "r"(addr))

#define MMA16816(c0, c1, c2, c3, a0, a1, a2, a3, b0, b1) \
    asm volatile("mma.sync.aligned.m16n8k16.row.col.f32.f16.f16.f32 " \
                 "{%0,%1,%2,%3}, {%4,%5,%6,%7}, {%8,%9}, {%0,%1,%2,%3};" \
                 : "+f"(c0), "+f"(c1), "+f"(c2), "+f"(c3) \
                 : "r"(a0), "r"(a1), "r"(a2), "r"(a3), "r"(b0), "r"(b1))

// ---------------------------------------------------------------------------
// Conversion kernels
// ---------------------------------------------------------------------------
__global__ void convert_x_kernel(const float* __restrict__ x, size_t total) {
    size_t i = ((size_t)blockIdx.x * blockDim.x + threadIdx.x) * 8;
    if (i >= total) return;
    float4 a = *reinterpret_cast<const float4*>(x + i);
    float4 b = *reinterpret_cast<const float4*>(x + i + 4);
    __half h[8];
    h[0] = __float2half_rn(a.x); h[1] = __float2half_rn(a.y);
    h[2] = __float2half_rn(a.z); h[3] = __float2half_rn(a.w);
    h[4] = __float2half_rn(b.x); h[5] = __float2half_rn(b.y);
    h[6] = __float2half_rn(b.z); h[7] = __float2half_rn(b.w);
    *reinterpret_cast<uint4*>(g_X + i) = *reinterpret_cast<uint4*>(h);
}

__global__ void dequant_kernel(const int* __restrict__ q,
                               const float* __restrict__ scales, int K) {
    size_t i = ((size_t)blockIdx.x * blockDim.x + threadIdx.x) * 8;
    int4 q0 = *reinterpret_cast<const int4*>(q + i);
    int4 q1 = *reinterpret_cast<const int4*>(q + i + 4);
    int k = (int)(i % (size_t)K);
    int n = (int)(i / (size_t)K);
    float s = scales[(size_t)n * (K >> 5) + (k >> 5)];
    __half h[8];
    h[0] = __float2half_rn(s * (float)(q0.x - 8));
    h[1] = __float2half_rn(s * (float)(q0.y - 8));
    h[2] = __float2half_rn(s * (float)(q0.z - 8));
    h[3] = __float2half_rn(s * (float)(q0.w - 8));
    h[4] = __float2half_rn(s * (float)(q1.x - 8));
    h[5] = __float2half_rn(s * (float)(q1.y - 8));
    h[6] = __float2half_rn(s * (float)(q1.z - 8));
    h[7] = __float2half_rn(s * (float)(q1.w - 8));
    *reinterpret_cast<uint4*>(g_W + i) = *reinterpret_cast<uint4*>(h);
}

// ---------------------------------------------------------------------------
// HMMA GEMM: 16 warps, warp grid 4(M) x 4(N), warp tile 32x64.
// Smem rows are 128B (BK=64 halves); chunk swizzle: sc = c ^ (row & 7).
// ---------------------------------------------------------------------------
__global__ void __launch_bounds__(THREADS, 1)
gemm_hmma_kernel(const float* __restrict__ bias, float* __restrict__ C,
                 int M, int N, int K) {
    extern __shared__ char smem[];
    const uint32_t smem_base = smem_u32(smem);
    const int tid = threadIdx.x;
    const int wid = tid >> 5;
    const int lane = tid & 31;

    const int bm = blockIdx.y * BM;
    const int bn = blockIdx.x * BN;

    const int warp_m = wid & 3;     // 4 warps over M (32 rows each)
    const int warp_n = wid >> 2;    // 4 warps over N (64 cols each)

    const __half* gA = g_X + (size_t)bm * K;
    const __half* gB = g_W + (size_t)bn * K;

    // Stage loader: A = 1024 16B-chunks (2/thread), B = 2048 (4/thread).
    auto load_stage = [&](int s, int kc) {
        const uint32_t sA = smem_base + s * STAGE_BYTES;
        const uint32_t sB = sA + A_STAGE_BYTES;
        const __half* gAk = gA + kc * BK;
        const __half* gBk = gB + kc * BK;
#pragma unroll
        for (int i = 0; i < 2; i++) {
            int cid = tid + (i << 9);          // 0..1023
            int row = cid >> 3, c = cid & 7;
            int sc = c ^ (row & 7);
            CP_ASYNC16(sA + row * 128 + (sc << 4),
                       gAk + (size_t)row * K + c * 8);
        }
#pragma unroll
        for (int i = 0; i < 4; i++) {
            int cid = tid + (i << 9);          // 0..2047
            int row = cid >> 3, c = cid & 7;
            int sc = c ^ (row & 7);
            CP_ASYNC16(sB + row * 128 + (sc << 4),
                       gBk + (size_t)row * K + c * 8);
        }
        CP_COMMIT();
    };

    // ldmatrix lane mapping (x4): lanes 0-15 pick rows (two 8x8 along rows),
    // lanes 16-31 the adjacent 16B k-chunk.
    const int rowoff = lane & 15;                 // 0..15
    const int csel   = (lane >> 4) & 1;           // 0/1
    const int swz    = rowoff & 7;

    const uint32_t aRowByte = (uint32_t)(warp_m * 32 + rowoff) * 128;
    const uint32_t bRowByte = (uint32_t)(warp_n * 64 + rowoff) * 128;

    float acc[2][8][4];
#pragma unroll
    for (int mt = 0; mt < 2; mt++)
#pragma unroll
        for (int j = 0; j < 8; j++)
#pragma unroll
            for (int r = 0; r < 4; r++) acc[mt][j][r] = 0.0f;

    const int nK = K / BK;   // 64 chunks

#pragma unroll
    for (int s = 0; s < STAGES - 1; s++) load_stage(s, s);

    int s = 0;
    for (int kc = 0; kc < nK; kc++) {
        CP_WAIT(STAGES - 2);
        __syncthreads();

        if (kc + STAGES - 1 < nK)
            load_stage((kc + STAGES - 1) % STAGES, kc + STAGES - 1);

        const uint32_t sA = smem_base + s * STAGE_BYTES;
        const uint32_t sB = sA + A_STAGE_BYTES;

#pragma unroll
        for (int ks = 0; ks < 4; ks++) {
            const int koff = (((ks << 1) + csel) ^ swz) << 4;
            uint32_t a[2][4];
#pragma unroll
            for (int mt = 0; mt < 2; mt++)
                LDSM_X4(a[mt][0], a[mt][1], a[mt][2], a[mt][3],
                        sA + aRowByte + mt * 2048 + koff);
            uint32_t b[4][4];
#pragma unroll
            for (int nt = 0; nt < 4; nt++)
                LDSM_X4(b[nt][0], b[nt][1], b[nt][2], b[nt][3],
                        sB + bRowByte + nt * 2048 + koff);
#pragma unroll
            for (int mt = 0; mt < 2; mt++)
#pragma unroll
                for (int j = 0; j < 8; j++) {
                    const int nt = j >> 1, odd = j & 1;
                    MMA16816(acc[mt][j][0], acc[mt][j][1],
                             acc[mt][j][2], acc[mt][j][3],
                             a[mt][0], a[mt][1], a[mt][2], a[mt][3],
                             b[nt][odd], b[nt][2 + odd]);
                }
        }
        s = (s + 1 == STAGES) ? 0 : s + 1;
        __syncthreads();
    }

    // Epilogue
    const int colb = bn + warp_n * 64 + (lane & 3) * 2;
    float2 brow[8];
#pragma unroll
    for (int j = 0; j < 8; j++)
        brow[j] = *reinterpret_cast<const float2*>(bias + colb + j * 8);

#pragma unroll
    for (int mt = 0; mt < 2; mt++) {
        const int row0 = bm + warp_m * 32 + mt * 16 + (lane >> 2);
#pragma unroll
        for (int j = 0; j < 8; j++) {
            const int col = colb + j * 8;
            float2 v0, v1;
            v0.x = acc[mt][j][0] + brow[j].x;
            v0.y = acc[mt][j][1] + brow[j].y;
            v1.x = acc[mt][j][2] + brow[j].x;
            v1.y = acc[mt][j][3] + brow[j].y;
            *reinterpret_cast<float2*>(C + (size_t)row0 * N + col) = v0;
            *reinterpret_cast<float2*>(C + (size_t)(row0 + 8) * N + col) = v1;
        }
    }
}

// ---------------------------------------------------------------------------
extern "C" void kernel_launch(void* const* d_in, const int* in_sizes, int n_in,
                              void* d_out, int out_size) {
    const float* x      = (const float*)d_in[0];
    const int*   qw     = (const int*)d_in[1];
    const float* scales = (const float*)d_in[2];
    const float* bias   = (const float*)d_in[3];
    float*       out    = (float*)d_out;

    const int N = in_sizes[3];           // 4096
    const int K = in_sizes[1] / N;       // 4096
    const int M = in_sizes[0] / K;       // 8192

    size_t xTotal = (size_t)M * K;
    size_t wTotal = (size_t)N * K;
    convert_x_kernel<<<(unsigned)((xTotal / 8 + 255) / 256), 256>>>(x, xTotal);
    dequant_kernel<<<(unsigned)((wTotal / 8 + 255) / 256), 256>>>(qw, scales, K);

    cudaFuncSetAttribute(gemm_hmma_kernel,
                         cudaFuncAttributeMaxDynamicSharedMemorySize, SMEM_TOTAL);

    dim3 grid(N / BN, M / BM);
    gemm_hmma_kernel<<<grid, THREADS, SMEM_TOTAL>>>(bias, out, M, N, K);
}

// round 10
// speedup vs baseline: 6.9592x; 1.0289x over previous
#include <cuda_runtime.h>
#include <cuda_fp16.h>
#include <cstdint>

// ===========================================================================
// GGUFWeight (sm_103 portable path): out = x @ W^T + bias,
// W = scale * (q - 8). M=8192, N=4096, K=4096.
// Phase 1 (single kernel): x -> fp16 g_X  and  dequant W -> fp16 g_W.
// Phase 2: mma.sync.m16n8k16 GEMM, 128x256 CTA tile, BK=64, 4-stage cp.async,
//          512 threads (16 warps, 4x4 warp grid, 32x64 warp tile),
//          SW128 XOR swizzle + ldmatrix.x4, fp32 accum, fused bias.
// ===========================================================================

#define THREADS 512
#define BM 128
#define BN 256
#define BK 64
#define STAGES 4
#define A_STAGE_BYTES (BM * 128)             // 128 rows * 128B (64 halves)
#define B_STAGE_BYTES (BN * 128)             // 256 rows * 128B
#define STAGE_BYTES (A_STAGE_BYTES + B_STAGE_BYTES)   // 49152
#define SMEM_TOTAL (STAGES * STAGE_BYTES)             // 196608

__device__ __half g_X[8192ull * 4096ull];   // [M,K] K-major fp16
__device__ __half g_W[4096ull * 4096ull];   // [N,K] K-major fp16

// ---------------------------------------------------------------------------
__device__ __forceinline__ uint32_t smem_u32(const void* p) {
    uint32_t a;
    asm("{ .reg .u64 t; cvta.to.shared.u64 t, %1; cvt.u32.u64 %0, t; }"
        : "=r"(a) : "l"(p));
    return a;
}

#define CP_ASYNC16(dst, src) \
    asm volatile("cp.async.cg.shared.global [%0], [%1], 16;" \
                 :: "r"(dst), "l"(src) : "memory")
#define CP_COMMIT() asm volatile("cp.async.commit_group;" ::: "memory")
#define CP_WAIT(n)  asm volatile("cp.async.wait_group %0;" :: "n"(n) : "memory")

#define LDSM_X4(r0, r1, r2, r3, addr) \
    asm volatile("ldmatrix.sync.aligned.m8n8.x4.shared.b16 {%0,%1,%2,%3}, [%4];" \
                 : "=r"(r0), "=r"(r1), "=r"(r2), "=r"(r3) : "r"(addr))

#define MMA16816(c0, c1, c2, c3, a0, a1, a2, a3, b0, b1) \
    asm volatile("mma.sync.aligned.m16n8k16.row.col.f32.f16.f16.f32 " \
                 "{%0,%1,%2,%3}, {%4,%5,%6,%7}, {%8,%9}, {%0,%1,%2,%3};" \
                 : "+f"(c0), "+f"(c1), "+f"(c2), "+f"(c3) \
                 : "r"(a0), "r"(a1), "r"(a2), "r"(a3), "r"(b0), "r"(b1))

// ---------------------------------------------------------------------------
// Fused conversion: blocks [0, xBlocks) convert x -> g_X fp16;
// blocks [xBlocks, xBlocks + wBlocks) dequant qweight -> g_W fp16.
// ---------------------------------------------------------------------------
__global__ void convert_all_kernel(const float* __restrict__ x,
                                   const int* __restrict__ q,
                                   const float* __restrict__ scales,
                                   int K, unsigned xBlocks) {
    if (blockIdx.x < xBlocks) {
        size_t i = ((size_t)blockIdx.x * blockDim.x + threadIdx.x) * 8;
        float4 a = *reinterpret_cast<const float4*>(x + i);
        float4 b = *reinterpret_cast<const float4*>(x + i + 4);
        __half h[8];
        h[0] = __float2half_rn(a.x); h[1] = __float2half_rn(a.y);
        h[2] = __float2half_rn(a.z); h[3] = __float2half_rn(a.w);
        h[4] = __float2half_rn(b.x); h[5] = __float2half_rn(b.y);
        h[6] = __float2half_rn(b.z); h[7] = __float2half_rn(b.w);
        *reinterpret_cast<uint4*>(g_X + i) = *reinterpret_cast<uint4*>(h);
    } else {
        size_t i = ((size_t)(blockIdx.x - xBlocks) * blockDim.x + threadIdx.x) * 8;
        int4 q0 = *reinterpret_cast<const int4*>(q + i);
        int4 q1 = *reinterpret_cast<const int4*>(q + i + 4);
        int k = (int)(i % (size_t)K);
        int n = (int)(i / (size_t)K);
        float s = scales[(size_t)n * (K >> 5) + (k >> 5)];
        __half h[8];
        h[0] = __float2half_rn(s * (float)(q0.x - 8));
        h[1] = __float2half_rn(s * (float)(q0.y - 8));
        h[2] = __float2half_rn(s * (float)(q0.z - 8));
        h[3] = __float2half_rn(s * (float)(q0.w - 8));
        h[4] = __float2half_rn(s * (float)(q1.x - 8));
        h[5] = __float2half_rn(s * (float)(q1.y - 8));
        h[6] = __float2half_rn(s * (float)(q1.z - 8));
        h[7] = __float2half_rn(s * (float)(q1.w - 8));
        *reinterpret_cast<uint4*>(g_W + i) = *reinterpret_cast<uint4*>(h);
    }
}

// ---------------------------------------------------------------------------
// HMMA GEMM: 16 warps, warp grid 4(M) x 4(N), warp tile 32x64.
// Smem rows are 128B (BK=64 halves); chunk swizzle: sc = c ^ (row & 7).
// ---------------------------------------------------------------------------
__global__ void __launch_bounds__(THREADS, 1)
gemm_hmma_kernel(const float* __restrict__ bias, float* __restrict__ C,
                 int M, int N, int K) {
    extern __shared__ char smem[];
    const uint32_t smem_base = smem_u32(smem);
    const int tid = threadIdx.x;
    const int wid = tid >> 5;
    const int lane = tid & 31;

    const int bm = blockIdx.y * BM;
    const int bn = blockIdx.x * BN;

    const int warp_m = wid & 3;     // 4 warps over M (32 rows each)
    const int warp_n = wid >> 2;    // 4 warps over N (64 cols each)

    const __half* gA = g_X + (size_t)bm * K;
    const __half* gB = g_W + (size_t)bn * K;

    auto load_stage = [&](int s, int kc) {
        const uint32_t sA = smem_base + s * STAGE_BYTES;
        const uint32_t sB = sA + A_STAGE_BYTES;
        const __half* gAk = gA + kc * BK;
        const __half* gBk = gB + kc * BK;
#pragma unroll
        for (int i = 0; i < 2; i++) {
            int cid = tid + (i << 9);          // 0..1023
            int row = cid >> 3, c = cid & 7;
            int sc = c ^ (row & 7);
            CP_ASYNC16(sA + row * 128 + (sc << 4),
                       gAk + (size_t)row * K + c * 8);
        }
#pragma unroll
        for (int i = 0; i < 4; i++) {
            int cid = tid + (i << 9);          // 0..2047
            int row = cid >> 3, c = cid & 7;
            int sc = c ^ (row & 7);
            CP_ASYNC16(sB + row * 128 + (sc << 4),
                       gBk + (size_t)row * K + c * 8);
        }
        CP_COMMIT();
    };

    const int rowoff = lane & 15;                 // 0..15
    const int csel   = (lane >> 4) & 1;           // 0/1
    const int swz    = rowoff & 7;

    const uint32_t aRowByte = (uint32_t)(warp_m * 32 + rowoff) * 128;
    const uint32_t bRowByte = (uint32_t)(warp_n * 64 + rowoff) * 128;

    float acc[2][8][4];
#pragma unroll
    for (int mt = 0; mt < 2; mt++)
#pragma unroll
        for (int j = 0; j < 8; j++)
#pragma unroll
            for (int r = 0; r < 4; r++) acc[mt][j][r] = 0.0f;

    const int nK = K / BK;   // 64 chunks

#pragma unroll
    for (int s = 0; s < STAGES - 1; s++) load_stage(s, s);

    int s = 0;
    for (int kc = 0; kc < nK; kc++) {
        CP_WAIT(STAGES - 2);
        // This barrier both publishes stage kc's data to all warps AND
        // guarantees every warp has finished reading stage kc-1 (read in the
        // previous iteration, which precedes this barrier in program order)
        // before load_stage below overwrites stage (kc+STAGES-1) % STAGES
        // == (kc-1) % STAGES. No trailing barrier needed.
        __syncthreads();

        if (kc + STAGES - 1 < nK)
            load_stage((kc + STAGES - 1) & (STAGES - 1), kc + STAGES - 1);

        const uint32_t sA = smem_base + s * STAGE_BYTES;
        const uint32_t sB = sA + A_STAGE_BYTES;

#pragma unroll
        for (int ks = 0; ks < 4; ks++) {
            const int koff = (((ks << 1) + csel) ^ swz) << 4;
            uint32_t a[2][4];
#pragma unroll
            for (int mt = 0; mt < 2; mt++)
                LDSM_X4(a[mt][0], a[mt][1], a[mt][2], a[mt][3],
                        sA + aRowByte + mt * 2048 + koff);
            uint32_t b[4][4];
#pragma unroll
            for (int nt = 0; nt < 4; nt++)
                LDSM_X4(b[nt][0], b[nt][1], b[nt][2], b[nt][3],
                        sB + bRowByte + nt * 2048 + koff);
#pragma unroll
            for (int mt = 0; mt < 2; mt++)
#pragma unroll
                for (int j = 0; j < 8; j++) {
                    const int nt = j >> 1, odd = j & 1;
                    MMA16816(acc[mt][j][0], acc[mt][j][1],
                             acc[mt][j][2], acc[mt][j][3],
                             a[mt][0], a[mt][1], a[mt][2], a[mt][3],
                             b[nt][odd], b[nt][2 + odd]);
                }
        }
        s = (s + 1) & (STAGES - 1);
    }

    // Epilogue
    const int colb = bn + warp_n * 64 + (lane & 3) * 2;
    float2 brow[8];
#pragma unroll
    for (int j = 0; j < 8; j++)
        brow[j] = *reinterpret_cast<const float2*>(bias + colb + j * 8);

#pragma unroll
    for (int mt = 0; mt < 2; mt++) {
        const int row0 = bm + warp_m * 32 + mt * 16 + (lane >> 2);
#pragma unroll
        for (int j = 0; j < 8; j++) {
            const int col = colb + j * 8;
            float2 v0, v1;
            v0.x = acc[mt][j][0] + brow[j].x;
            v0.y = acc[mt][j][1] + brow[j].y;
            v1.x = acc[mt][j][2] + brow[j].x;
            v1.y = acc[mt][j][3] + brow[j].y;
            *reinterpret_cast<float2*>(C + (size_t)row0 * N + col) = v0;
            *reinterpret_cast<float2*>(C + (size_t)(row0 + 8) * N + col) = v1;
        }
    }
}

// ---------------------------------------------------------------------------
extern "C" void kernel_launch(void* const* d_in, const int* in_sizes, int n_in,
                              void* d_out, int out_size) {
    const float* x      = (const float*)d_in[0];
    const int*   qw     = (const int*)d_in[1];
    const float* scales = (const float*)d_in[2];
    const float* bias   = (const float*)d_in[3];
    float*       out    = (float*)d_out;

    const int N = in_sizes[3];           // 4096
    const int K = in_sizes[1] / N;       // 4096
    const int M = in_sizes[0] / K;       // 8192

    size_t xTotal = (size_t)M * K;
    size_t wTotal = (size_t)N * K;
    unsigned xBlocks = (unsigned)(xTotal / 8 / 256);   // 8192*4096/8/256 = 16384
    unsigned wBlocks = (unsigned)(wTotal / 8 / 256);   // 8192
    convert_all_kernel<<<xBlocks + wBlocks, 256>>>(x, qw, scales, K, xBlocks);

    cudaFuncSetAttribute(gemm_hmma_kernel,
                         cudaFuncAttributeMaxDynamicSharedMemorySize, SMEM_TOTAL);

    dim3 grid(N / BN, M / BM);
    gemm_hmma_kernel<<<grid, THREADS, SMEM_TOTAL>>>(bias, out, M, N, K);
}